// round 8
// baseline (speedup 1.0000x reference)
#include <cuda_runtime.h>
#include <math.h>
#include <stdint.h>

#define H 2048
#define W 2048
#define OH 2046
#define OW 2046
#define TILE 32
#define HALO 34
#define PTS  (HALO * HALO)       // 1156
#define SROW 36                  // E/V row stride (floats) = 144 B bulk row
#define SSROW 104                // strain row stride (floats) = 416 B bulk row
#define NT   4096                // 64x64 tiles
#define NB   592                 // 4 blocks/SM * 148 SMs

// Deterministic per-block partials; last block (atomic ticket) reduces in fixed order.
__device__ double2 g_part[NB];
__device__ unsigned int g_count;   // zero at load; last block resets -> replay-safe

__device__ __forceinline__ uint32_t s2u(const void* p) {
    return (uint32_t)__cvta_generic_to_shared(p);
}
__device__ __forceinline__ void bulk_g2s(uint32_t dst, const float* src, int bytes, uint32_t mbar) {
    asm volatile(
        "cp.async.bulk.shared::cluster.global.mbarrier::complete_tx::bytes [%0], [%1], %2, [%3];"
        :: "r"(dst), "l"(src), "r"(bytes), "r"(mbar) : "memory");
}
__device__ __forceinline__ void mbar_init(uint32_t mbar, int count) {
    asm volatile("mbarrier.init.shared.b64 [%0], %1;" :: "r"(mbar), "r"(count) : "memory");
}
__device__ __forceinline__ void mbar_expect_tx(uint32_t mbar, int bytes) {
    asm volatile("mbarrier.arrive.expect_tx.shared.b64 _, [%0], %1;"
                 :: "r"(mbar), "r"(bytes) : "memory");
}
__device__ __forceinline__ void mbar_wait(uint32_t mbar, int parity) {
    asm volatile(
        "{\n\t.reg .pred P;\n"
        "LW_%=:\n\t"
        "mbarrier.try_wait.parity.shared.b64 P, [%0], %1;\n\t"
        "@P bra LD_%=;\n\t"
        "bra LW_%=;\n"
        "LD_%=:\n\t}"
        :: "r"(mbar), "r"(parity) : "memory");
}
#define FENCE_ASYNC() asm volatile("fence.proxy.async.shared::cta;" ::: "memory")

__global__ __launch_bounds__(256, 4)
void inverse_loss_tma(const float* __restrict__ predE,
                      const float* __restrict__ predV,
                      const float* __restrict__ strain,
                      float* __restrict__ out)
{
    __shared__ alignas(16) float sE[2][HALO * SROW];
    __shared__ alignas(16) float sV[2][HALO * SROW];
    __shared__ alignas(16) float sS[2][HALO * SSROW];
    __shared__ alignas(8)  unsigned long long mbar[2];
    __shared__ float wl[8], we[8];
    __shared__ double swl[8], swe[8];
    __shared__ int sIsLast;

    const int tid    = threadIdx.x;
    const int lx     = tid & 31;
    const int lybase = (tid >> 5) * 4;

    if (tid == 0) {
        mbar_init(s2u(&mbar[0]), 2);
        mbar_init(s2u(&mbar[1]), 2);
        FENCE_ASYNC();
    }
    __syncthreads();

    const uint32_t mb[2] = { s2u(&mbar[0]), s2u(&mbar[1]) };

    // ---- issue one tile's bulk loads into stage st (tid0: E+V, tid32: strain) ----
    auto issue = [&](int t, int st) {
        const int oy0  = (t >> 6) * TILE;
        const int ox0  = (t & 63) * TILE;
        const int rows = (oy0 + HALO <= H) ? HALO : (H - oy0);       // 34 or 32
        const bool xe  = (ox0 + HALO > W);                           // right-edge tile
        if (tid == 0) {
            const int evb = xe ? 128 : 144;
            mbar_expect_tx(mb[st], 2 * rows * evb);
            const float* eg = predE + oy0 * W + ox0;
            const float* vg = predV + oy0 * W + ox0;
            const uint32_t de = s2u(&sE[st][0]);
            const uint32_t dv = s2u(&sV[st][0]);
            for (int y = 0; y < rows; y++) {
                bulk_g2s(de + y * (SROW * 4), eg + y * W, evb, mb[st]);
                bulk_g2s(dv + y * (SROW * 4), vg + y * W, evb, mb[st]);
            }
        } else if (tid == 32) {
            const int sb = xe ? 384 : 416;
            mbar_expect_tx(mb[st], rows * sb);
            const float* sg = strain + 3 * (oy0 * W + ox0);
            const uint32_t ds = s2u(&sS[st][0]);
            for (int y = 0; y < rows; y++)
                bulk_g2s(ds + y * (SSROW * 4), sg + y * 3 * W, sb, mb[st]);
        }
    };

    const int t0 = blockIdx.x;
    float lsum = 0.f, esum = 0.f;
    int ph0 = 0, ph1 = 0;

    issue(t0, 0);

    int k = 0;
    for (int t = t0; t < NT; t += NB, k++) {
        const int tn = t + NB;
        if (tn < NT) issue(tn, (k + 1) & 1);

        const int st = k & 1;
        // wait for this tile's data (acquire: no extra __syncthreads needed)
        if (st == 0) { mbar_wait(mb[0], ph0); ph0 ^= 1; }
        else         { mbar_wait(mb[1], ph1); ph1 ^= 1; }

        const float* __restrict__ e_ = sE[st];
        const float* __restrict__ v_ = sV[st];
        float* __restrict__ s_ = sS[st];

        // ---- phase 1: stress transform in place over strain; E-mean rides along ----
        #pragma unroll
        for (int i = 0; i < 5; i++) {
            const int p = tid + i * 256;
            if (p < PTS) {
                const int y = p / HALO, x = p - y * HALO;
                const float e = e_[y * SROW + x];
                const float v = v_[y * SROW + x];
                if (x < TILE && y < TILE) esum += e;   // exact interior partition
                const int si = y * SSROW + 3 * x;
                const float exx = s_[si], eyy = s_[si + 1], exy = s_[si + 2];
                const float frac = __fdividef(e, 1.0f - v * v);
                s_[si]     = (exx + v * eyy) * frac;
                s_[si + 1] = (v * exx + eyy) * frac;
                s_[si + 2] = exy * (1.0f - v) * 0.5f * frac;
            }
        }
        __syncthreads();

        // ---- phase 2: stencil, 1 column x 4 output rows per thread ----
        float rsE[6], rsXX[6], rsXY[6], dYY[6], dXY[6];
        #pragma unroll
        for (int r = 0; r < 6; r++) {
            const int eb = (lybase + r) * SROW + lx;
            rsE[r] = e_[eb] + e_[eb + 1] + e_[eb + 2];
            const int sb = (lybase + r) * SSROW + 3 * lx;
            const float xx0 = s_[sb],     yy0 = s_[sb + 1], xy0 = s_[sb + 2];
            const float xx1 = s_[sb + 3],                   xy1 = s_[sb + 5];
            const float xx2 = s_[sb + 6], yy2 = s_[sb + 7], xy2 = s_[sb + 8];
            rsXX[r] = xx0 + xx1 + xx2;
            rsXY[r] = xy0 + xy1 + xy2;
            dYY[r]  = yy0 - yy2;
            dXY[r]  = xy0 - xy2;
        }

        const int oy0 = (t >> 6) * TILE;
        const int ox  = (t & 63) * TILE + lx;
        #pragma unroll
        for (int q = 0; q < 4; q++) {
            const int oy = oy0 + lybase + q;
            if (oy < OH && ox < OW) {
                const float Ec = rsE[q] + rsE[q + 1] + rsE[q + 2];
                const float fx = (rsXX[q + 2] - rsXX[q]) + (dXY[q] + dXY[q + 1] + dXY[q + 2]);
                const float fy = (dYY[q] + dYY[q + 1] + dYY[q + 2]) + (rsXY[q + 2] - rsXY[q]);
                lsum += __fdividef(fabsf(fx) + fabsf(fy), Ec);
            }
        }

        // order generic reads of this stage before next iteration's async overwrite
        FENCE_ASYNC();
        __syncthreads();
    }

    // ---- block reduction ----
    #pragma unroll
    for (int o = 16; o > 0; o >>= 1) {
        lsum += __shfl_down_sync(0xffffffffu, lsum, o);
        esum += __shfl_down_sync(0xffffffffu, esum, o);
    }
    if ((tid & 31) == 0) { wl[tid >> 5] = lsum; we[tid >> 5] = esum; }
    __syncthreads();
    if (tid == 0) {
        double L = 0.0, Es = 0.0;
        #pragma unroll
        for (int i = 0; i < 8; i++) { L += (double)wl[i]; Es += (double)we[i]; }
        g_part[blockIdx.x] = make_double2(L, Es);
        __threadfence();
        const unsigned prev = atomicAdd(&g_count, 1u);
        sIsLast = (prev == NB - 1u) ? 1 : 0;
    }
    __syncthreads();

    // ---- last block: deterministic final reduction over 592 partials ----
    if (sIsLast) {
        double L = 0.0, E = 0.0;
        for (int i = tid; i < NB; i += 256) {
            const double2 v = g_part[i];
            L += v.x; E += v.y;
        }
        #pragma unroll
        for (int o = 16; o > 0; o >>= 1) {
            L += __shfl_down_sync(0xffffffffu, L, o);
            E += __shfl_down_sync(0xffffffffu, E, o);
        }
        if ((tid & 31) == 0) { swl[tid >> 5] = L; swe[tid >> 5] = E; }
        __syncthreads();
        if (tid == 0) {
            double Lt = 0.0, Et = 0.0;
            #pragma unroll
            for (int i = 0; i < 8; i++) { Lt += swl[i]; Et += swe[i]; }
            const double M = (double)OH * (double)OW;
            const double meanE = Et / ((double)H * (double)W);
            out[0] = (float)(Lt / M + fabs(meanE - 1.0) / 100.0);
            g_count = 0;   // reset for next graph replay
        }
    }
}

extern "C" void kernel_launch(void* const* d_in, const int* in_sizes, int n_in,
                              void* d_out, int out_size)
{
    const float* predE  = (const float*)d_in[0];
    const float* predV  = (const float*)d_in[1];
    const float* strain = (const float*)d_in[2];
    float* out = (float*)d_out;

    inverse_loss_tma<<<NB, 256>>>(predE, predV, strain, out);
}